// round 1
// baseline (speedup 1.0000x reference)
#include <cuda_runtime.h>

// ---------------- problem constants ----------------
#define IMG   640
#define HW    (IMG*IMG)
#define Bc    2
#define Dc    96
#define INC   3
#define Pp    4
#define HP    160
#define NTOK  (HP*HP)            // 25600 tokens per batch
#define TOK_ELEMS (Bc*NTOK*Dc)   // 4,915,200
#define LN_EPS 1e-5f

// ---------------- scratch (device globals; no allocs allowed) ----------------
__device__ float g_xe[Bc*Dc*HW];   // x_embed, NCHW
__device__ float g_h [Bc*Dc*HW];   // gelu(conv3x3), NCHW
__device__ float g_mx[Bc*NTOK];
__device__ float g_my[Bc*NTOK];
__device__ float g_s [Bc*NTOK];

// ---------------- helpers ----------------
__device__ __forceinline__ unsigned long long pk2(float v) {
    unsigned long long r;
    asm("mov.b64 %0, {%1, %1};" : "=l"(r) : "f"(v));
    return r;
}
__device__ __forceinline__ void fma2(unsigned long long& acc,
                                     unsigned long long a,
                                     unsigned long long b) {
    asm("fma.rn.f32x2 %0, %1, %2, %0;" : "+l"(acc) : "l"(a), "l"(b));
}
__device__ __forceinline__ float2 upk2(unsigned long long v) {
    float2 r;
    asm("mov.b64 {%0, %1}, %2;" : "=f"(r.x), "=f"(r.y) : "l"(v));
    return r;
}
__device__ __forceinline__ float gelu_exact(float v) {
    return 0.5f * v * (1.0f + erff(v * 0.7071067811865476f));
}

// ============================================================================
// Kernel 1: x_embed[b,d,y,x] = sum_c x[b,c,y,x]*ew[d,c] + eb[d]
// ============================================================================
__global__ void k_embed(const float* __restrict__ x,
                        const float* __restrict__ ew,
                        const float* __restrict__ eb) {
    __shared__ float sw[Dc*INC];
    __shared__ float sb[Dc];
    for (int i = threadIdx.x; i < Dc*INC; i += blockDim.x) sw[i] = ew[i];
    for (int i = threadIdx.x; i < Dc;     i += blockDim.x) sb[i] = eb[i];
    __syncthreads();
    int t = blockIdx.x * blockDim.x + threadIdx.x;
    if (t >= Bc*HW) return;
    int b = t / HW, p = t % HW;
    float x0 = x[(b*INC + 0)*HW + p];
    float x1 = x[(b*INC + 1)*HW + p];
    float x2 = x[(b*INC + 2)*HW + p];
    float* outb = g_xe + b*Dc*HW + p;
#pragma unroll 8
    for (int d = 0; d < Dc; d++) {
        outb[d*HW] = sw[d*3+0]*x0 + sw[d*3+1]*x1 + sw[d*3+2]*x2 + sb[d];
    }
}

// ============================================================================
// Kernel 2: h = gelu(conv3x3(x_embed, w1) + b1), SAME zero-pad.
// Tile: 32 do x 8 y x 64 x per block, di-chunks of 8.
// Thread: 8 do x 2 y x 4 x, packed f32x2 accumulators over do-pairs.
// ============================================================================
#define CH 8
__global__ void __launch_bounds__(256) k_conv(const float* __restrict__ w1,
                                              const float* __restrict__ b1) {
    __shared__ float A[CH][10][68];     // halo tile: 10 rows x 66 cols (+pad)
    __shared__ float Wsh[CH][9][32];    // [di][k][do_local]

    const int tid = threadIdx.x;
    const int tx = tid & 15;            // x-quad index   (16)
    const int ty = (tid >> 4) & 3;      // y-pair index   (4)
    const int g  = tid >> 6;            // do-group       (4)

    const int x0  = blockIdx.x * 64;
    const int y0  = blockIdx.y * 8;
    const int bz  = blockIdx.z;         // b*3 + do-tile
    const int b   = bz / 3;
    const int do0 = (bz % 3) * 32;

    unsigned long long acc[2][4][4];    // [py][px][do-pair]
#pragma unroll
    for (int py = 0; py < 2; py++)
#pragma unroll
        for (int qx = 0; qx < 4; qx++)
#pragma unroll
            for (int j = 0; j < 4; j++) acc[py][qx][j] = 0ULL;

    for (int dic = 0; dic < Dc; dic += CH) {
        __syncthreads();
        // load x_embed halo tile (rows y0-1..y0+8, cols x0-1..x0+64)
        for (int idx = tid; idx < CH*10*66; idx += 256) {
            int c  = idx % 66;
            int r  = (idx / 66) % 10;
            int ch = idx / 660;
            int gx = x0 - 1 + c;
            int gy = y0 - 1 + r;
            float v = 0.0f;
            if ((unsigned)gx < (unsigned)IMG && (unsigned)gy < (unsigned)IMG)
                v = g_xe[((b*Dc + dic + ch)*IMG + gy)*IMG + gx];
            A[ch][r][c] = v;
        }
        // load weights: Wsh[ch][k][dol] = w1[(do0+dol)*96 + dic+ch][k]
        for (int idx = tid; idx < CH*9*32; idx += 256) {
            int dol = idx & 31;
            int k   = (idx >> 5) % 9;
            int ch  = idx / 288;
            Wsh[ch][k][dol] = w1[((do0 + dol)*Dc + (dic + ch))*9 + k];
        }
        __syncthreads();

#pragma unroll
        for (int ch = 0; ch < CH; ch++) {
#pragma unroll
            for (int ky = 0; ky < 3; ky++) {
                unsigned long long vp[2][6];
#pragma unroll
                for (int r = 0; r < 2; r++)
#pragma unroll
                    for (int c = 0; c < 6; c++)
                        vp[r][c] = pk2(A[ch][ty*2 + ky + r][tx*4 + c]);
#pragma unroll
                for (int kx = 0; kx < 3; kx++) {
                    unsigned long long wv[4];
#pragma unroll
                    for (int j = 0; j < 4; j++)
                        wv[j] = *(const unsigned long long*)(&Wsh[ch][ky*3 + kx][g*8 + 2*j]);
#pragma unroll
                    for (int py = 0; py < 2; py++)
#pragma unroll
                        for (int qx = 0; qx < 4; qx++)
#pragma unroll
                            for (int j = 0; j < 4; j++)
                                fma2(acc[py][qx][j], vp[py][qx + kx], wv[j]);
                }
            }
        }
    }

    // epilogue: bias + gelu + store
    const int Y = y0 + ty*2;
    const int X = x0 + tx*4;
#pragma unroll
    for (int j = 0; j < 4; j++) {
        int d0 = do0 + g*8 + 2*j;
        float bb0 = b1[d0], bb1 = b1[d0 + 1];
#pragma unroll
        for (int py = 0; py < 2; py++)
#pragma unroll
            for (int qx = 0; qx < 4; qx++) {
                float2 v = upk2(acc[py][qx][j]);
                int base = ((b*Dc + d0)*IMG + (Y + py))*IMG + (X + qx);
                g_h[base]      = gelu_exact(v.x + bb0);
                g_h[base + HW] = gelu_exact(v.y + bb1);
            }
    }
}

// ============================================================================
// Kernel 3: params (4x4 stride-4 conv to 3 ch) -> mx, my, s (+scale_map out)
// One block per (b, py) row: 160 threads, each owns one px.
// ============================================================================
__global__ void __launch_bounds__(160) k_params(const float* __restrict__ w2,
                                                const float* __restrict__ b2,
                                                float* __restrict__ out_scale) {
    __shared__ float sh[4][IMG];       // 4 h-rows for current di
    __shared__ float sw2[3*Dc*16];     // (o*96+di)*16 + k

    const int b  = blockIdx.x / HP;
    const int py = blockIdx.x % HP;
    const int px = threadIdx.x;

    for (int i = threadIdx.x; i < 3*Dc*16; i += 160) sw2[i] = w2[i];

    float p0 = 0.f, p1 = 0.f, p2 = 0.f;
    for (int di = 0; di < Dc; di++) {
        __syncthreads();
        const float* hrow = g_h + ((b*Dc + di)*IMG + 4*py)*IMG;
        for (int i = threadIdx.x; i < 4*IMG; i += 160)
            sh[i / IMG][i % IMG] = hrow[i];
        __syncthreads();
#pragma unroll
        for (int k = 0; k < 16; k++) {
            float hv = sh[k >> 2][px*4 + (k & 3)];
            p0 = fmaf(hv, sw2[(0*Dc + di)*16 + k], p0);
            p1 = fmaf(hv, sw2[(1*Dc + di)*16 + k], p1);
            p2 = fmaf(hv, sw2[(2*Dc + di)*16 + k], p2);
        }
    }
    p0 += b2[0]; p1 += b2[1]; p2 += b2[2];

    float mx = 2.0f * tanhf(p0);
    float my = 2.0f * tanhf(p1);
    float s  = expf(tanhf(p2));
    s = fminf(fmaxf(s, 0.5f), 2.0f);

    int n = blockIdx.x * HP + px;     // b*25600 + py*160 + px
    g_mx[n] = mx; g_my[n] = my; g_s[n] = s;
    out_scale[n] = s;
}

// ============================================================================
// Kernel 4: deformable sampling + mean + embed + LayerNorm.
// Linearity: mean(bilerp(embed(x))) == embed(mean(bilerp(x))) since bilerp
// and the 16-sample mean are convex combinations (weights sum to 1).
// One warp per token. Lanes 0..15 each bilerp one of the 16 sample points
// on the 3-channel input; warp-reduce to the mean; then 3 embed channels per
// lane + warp LayerNorm over D=96.
// ============================================================================
__global__ void __launch_bounds__(256) k_sample(const float* __restrict__ x,
                                                const float* __restrict__ ew,
                                                const float* __restrict__ eb,
                                                const float* __restrict__ lnw,
                                                const float* __restrict__ lnb,
                                                float* __restrict__ out_tokens) {
    const int warp = (blockIdx.x * 256 + threadIdx.x) >> 5;
    const int lane = threadIdx.x & 31;
    if (warp >= Bc*NTOK) return;
    const int b  = warp / NTOK;
    const int n  = warp % NTOK;
    const int py = n / HP;
    const int px = n % HP;

    const float mx = g_mx[warp], my = g_my[warp], s = g_s[warp];
    const float cx = px*4 + 2.0f;
    const float cy = py*4 + 2.0f;
    const float half = s * 2.0f;

    const float x1 = fminf(fmaxf(cx + mx - half, 0.0f), 639.0f);
    const float x2 = fminf(fmaxf(cx + mx + half, 0.0f), 639.0f);
    const float y1 = fminf(fmaxf(cy + my - half, 0.0f), 639.0f);
    const float y2 = fminf(fmaxf(cy + my + half, 0.0f), 639.0f);

    float m0 = 0.f, m1 = 0.f, m2 = 0.f;
    if (lane < 16) {
        const int i = lane & 3;     // x index (fast axis in reference)
        const int j = lane >> 2;    // y index
        const float xt = x1 + (x2 - x1) * (i * (1.0f/3.0f));
        const float yt = y1 + (y2 - y1) * (j * (1.0f/3.0f));
        const float xf = floorf(xt), yf = floorf(yt);
        const float wx = xt - xf,   wy = yt - yf;
        int X0 = min(max((int)xf, 0), IMG-1);
        int X1 = min(X0 + 1, IMG-1);
        int Y0 = min(max((int)yf, 0), IMG-1);
        int Y1 = min(Y0 + 1, IMG-1);
        const float w00 = (1.f-wx)*(1.f-wy), w01 = wx*(1.f-wy);
        const float w10 = (1.f-wx)*wy,       w11 = wx*wy;
        const float* xb = x + b*INC*HW;
#pragma unroll
        for (int c = 0; c < INC; c++) {
            const float* f = xb + c*HW;
            float v = f[Y0*IMG + X0]*w00 + f[Y0*IMG + X1]*w01
                    + f[Y1*IMG + X0]*w10 + f[Y1*IMG + X1]*w11;
            if (c == 0) m0 = v; else if (c == 1) m1 = v; else m2 = v;
        }
    }
#pragma unroll
    for (int o = 16; o > 0; o >>= 1) {
        m0 += __shfl_xor_sync(0xFFFFFFFFu, m0, o);
        m1 += __shfl_xor_sync(0xFFFFFFFFu, m1, o);
        m2 += __shfl_xor_sync(0xFFFFFFFFu, m2, o);
    }
    m0 *= (1.0f/16.0f); m1 *= (1.0f/16.0f); m2 *= (1.0f/16.0f);

    // embed: 3 output channels per lane (d = lane, lane+32, lane+64)
    float t[3];
#pragma unroll
    for (int r = 0; r < 3; r++) {
        int d = lane + 32*r;
        t[r] = ew[d*3+0]*m0 + ew[d*3+1]*m1 + ew[d*3+2]*m2 + eb[d];
    }
    float lsum = t[0] + t[1] + t[2];
#pragma unroll
    for (int o = 16; o > 0; o >>= 1) lsum += __shfl_xor_sync(0xFFFFFFFFu, lsum, o);
    const float mu = lsum * (1.0f/96.0f);
    float d0 = t[0]-mu, d1 = t[1]-mu, d2 = t[2]-mu;
    float lsq = d0*d0 + d1*d1 + d2*d2;
#pragma unroll
    for (int o = 16; o > 0; o >>= 1) lsq += __shfl_xor_sync(0xFFFFFFFFu, lsq, o);
    const float var = lsq * (1.0f/96.0f);
    const float inv = 1.0f / sqrtf(var + LN_EPS);

    float* outw = out_tokens + warp*Dc;
#pragma unroll
    for (int r = 0; r < 3; r++) {
        int d = lane + 32*r;
        outw[d] = (t[r] - mu) * inv * lnw[d] + lnb[d];
    }
}

// ============================================================================
extern "C" void kernel_launch(void* const* d_in, const int* in_sizes, int n_in,
                              void* d_out, int out_size) {
    const float* x   = (const float*)d_in[0];
    const float* ew  = (const float*)d_in[1];
    const float* eb  = (const float*)d_in[2];
    const float* w1  = (const float*)d_in[3];
    const float* b1  = (const float*)d_in[4];
    const float* w2  = (const float*)d_in[5];
    const float* b2  = (const float*)d_in[6];
    const float* lnw = (const float*)d_in[7];
    const float* lnb = (const float*)d_in[8];
    float* out = (float*)d_out;

    // tokens first (2*25600*96), then scale_map (2*1*160*160)
    float* out_tokens = out;
    float* out_scale  = out + TOK_ELEMS;

    k_embed<<<(Bc*HW + 255)/256, 256>>>(x, ew, eb);

    dim3 gconv(IMG/64, IMG/8, Bc*3);
    k_conv<<<gconv, 256>>>(w1, b1);

    k_params<<<Bc*HP, 160>>>(w2, b2, out_scale);

    k_sample<<<(Bc*NTOK*32 + 255)/256, 256>>>(x, ew, eb, lnw, lnb, out_tokens);
}

// round 3
// speedup vs baseline: 12.3267x; 12.3267x over previous
#include <cuda_runtime.h>

// ---------------- problem constants ----------------
#define IMG   640
#define HW    (IMG*IMG)
#define Bc    2
#define Dc    96
#define HP    160
#define NTOK  (HP*HP)            // 25600 tokens per batch
#define TOK_ELEMS (Bc*NTOK*Dc)   // 4,915,200
#define LN_EPS 1e-5f

typedef unsigned long long ull;

// ---------------- scratch (device globals; no allocs allowed) ----------------
__device__ ull   g_wp [48*37];       // folded conv weights, f32x2 do-pairs: [dp][tap] tap36=b1
__device__ ull   g_w2p[3*48*16];     // second-conv weights, f32x2 do-pairs: [o][dp][tap]
__device__ float g_mx[Bc*NTOK];
__device__ float g_my[Bc*NTOK];
__device__ float g_s [Bc*NTOK];

// ---------------- helpers ----------------
__device__ __forceinline__ ull pk2(float v) {
    ull r; asm("mov.b64 %0, {%1, %1};" : "=l"(r) : "f"(v)); return r;
}
__device__ __forceinline__ ull pack2(float a, float b) {
    ull r; asm("mov.b64 %0, {%1, %2};" : "=l"(r) : "f"(a), "f"(b)); return r;
}
__device__ __forceinline__ void fma2(ull& acc, ull a, ull b) {
    asm("fma.rn.f32x2 %0, %1, %2, %0;" : "+l"(acc) : "l"(a), "l"(b));
}
__device__ __forceinline__ ull add2(ull a, ull b) {
    ull r; asm("add.rn.f32x2 %0, %1, %2;" : "=l"(r) : "l"(a), "l"(b)); return r;
}
__device__ __forceinline__ float2 upk2(ull v) {
    float2 r; asm("mov.b64 {%0, %1}, %2;" : "=f"(r.x), "=f"(r.y) : "l"(v)); return r;
}
__device__ __forceinline__ float gelu_exact(float v) {
    return 0.5f * v * (1.0f + erff(v * 0.7071067811865476f));
}

// ============================================================================
// Kernel A: fold embed (1x1) into the 3x3 conv -> w_eff over 4 channels
// (3 image channels + ones-channel carrying embed bias through zero padding),
// packed as f32x2 over output-channel pairs. Also pack w2 into do-pairs.
// ============================================================================
__global__ void k_weff(const float* __restrict__ ew,  // [96][3]
                       const float* __restrict__ eb,  // [96]
                       const float* __restrict__ w1,  // [96][96][3][3]
                       const float* __restrict__ b1,  // [96]
                       const float* __restrict__ w2)  // [3][96][4][4]
{
    const int gt = blockIdx.x * blockDim.x + threadIdx.x;
    const int gs = gridDim.x * blockDim.x;

    for (int idx = gt; idx < 48*37; idx += gs) {
        const int dp = idx / 37, t = idx % 37;
        float v0, v1;
        if (t == 36) { v0 = b1[2*dp]; v1 = b1[2*dp+1]; }
        else {
            const int c = t / 9, kk = t % 9;
            v0 = 0.f; v1 = 0.f;
            for (int di = 0; di < Dc; di++) {
                const float e  = (c < 3) ? ew[di*3 + c] : eb[di];
                v0 = fmaf(w1[((2*dp    )*Dc + di)*9 + kk], e, v0);
                v1 = fmaf(w1[((2*dp + 1)*Dc + di)*9 + kk], e, v1);
            }
        }
        g_wp[idx] = pack2(v0, v1);
    }

    for (int idx = gt; idx < 3*48*16; idx += gs) {
        const int tap = idx & 15;
        const int dp  = (idx >> 4) % 48;
        const int o   = idx / (48*16);
        g_w2p[idx] = pack2(w2[(o*Dc + 2*dp    )*16 + tap],
                           w2[(o*Dc + 2*dp + 1)*16 + tap]);
    }
}

// ============================================================================
// Kernel B: fully fused  conv3x3(4ch) + GELU + conv4x4-stride4 + transforms.
// CTA = 16x16 h-pixels = 4x4 params. Thread = one h pixel (36-reg x patch),
// loops 48 do-pairs with f32x2; contracts GELU'd h directly into 3 params.
// Width-16 shfl reduce finishes each param; lane 0 applies tanh/exp.
// ============================================================================
__global__ void __launch_bounds__(256) k_fused(const float* __restrict__ x,
                                               const float* __restrict__ b2,
                                               float* __restrict__ out_scale)
{
    __shared__ float sx[4][18][20];     // [c][row][col] halo tile (+pad)
    __shared__ ull   swp[48][37];       // folded conv weight pairs (+bias)
    __shared__ ull   sw2p[3][48][16];   // second conv weight pairs

    const int tid = threadIdx.x;
    const int b   = blockIdx.z;
    const int X0  = blockIdx.x * 16;
    const int Y0  = blockIdx.y * 16;

    for (int i = tid; i < 4*18*18; i += 256) {
        const int c   = i / (18*18);
        const int r   = (i / 18) % 18;
        const int col = i % 18;
        const int gy = Y0 - 1 + r;
        const int gx = X0 - 1 + col;
        const bool in = ((unsigned)gy < (unsigned)IMG) && ((unsigned)gx < (unsigned)IMG);
        float v;
        if (c < 3) v = in ? x[((b*3 + c)*IMG + gy)*IMG + gx] : 0.f;
        else       v = in ? 1.f : 0.f;
        sx[c][r][col] = v;
    }
    for (int i = tid; i < 48*37;   i += 256) ((ull*)swp )[i] = g_wp[i];
    for (int i = tid; i < 3*48*16; i += 256) ((ull*)sw2p)[i] = g_w2p[i];
    __syncthreads();

    const int p   = tid >> 4;          // param within CTA (0..15)
    const int tap = tid & 15;          // position within 4x4 patch
    const int hy  = (p >> 2) * 4 + (tap >> 2);
    const int hx  = (p &  3) * 4 + (tap &  3);

    // register-cache the 4x3x3 input patch, pre-broadcast to f32x2
    ull xp2[36];
#pragma unroll
    for (int c = 0; c < 4; c++)
#pragma unroll
        for (int ky = 0; ky < 3; ky++)
#pragma unroll
            for (int kx = 0; kx < 3; kx++)
                xp2[c*9 + ky*3 + kx] = pk2(sx[c][hy + ky][hx + kx]);

    ull pa0 = 0ULL, pa1 = 0ULL, pa2 = 0ULL;
#pragma unroll 2
    for (int dp = 0; dp < 48; dp++) {
        ull a0 = swp[dp][36];          // (b1[2dp], b1[2dp+1]) pre-gelu bias
        ull a1 = 0ULL;
#pragma unroll
        for (int t = 0; t < 36; t += 2) {
            fma2(a0, xp2[t],     swp[dp][t]);
            fma2(a1, xp2[t + 1], swp[dp][t + 1]);
        }
        const float2 hv = upk2(add2(a0, a1));
        const ull hp = pack2(gelu_exact(hv.x), gelu_exact(hv.y));
        fma2(pa0, hp, sw2p[0][dp][tap]);
        fma2(pa1, hp, sw2p[1][dp][tap]);
        fma2(pa2, hp, sw2p[2][dp][tap]);
    }

    const float2 q0 = upk2(pa0), q1 = upk2(pa1), q2 = upk2(pa2);
    float p0 = q0.x + q0.y;
    float p1 = q1.x + q1.y;
    float p2 = q2.x + q2.y;
#pragma unroll
    for (int off = 8; off > 0; off >>= 1) {
        p0 += __shfl_down_sync(0xFFFFFFFFu, p0, off, 16);
        p1 += __shfl_down_sync(0xFFFFFFFFu, p1, off, 16);
        p2 += __shfl_down_sync(0xFFFFFFFFu, p2, off, 16);
    }
    if (tap == 0) {
        p0 += b2[0]; p1 += b2[1]; p2 += b2[2];
        const float mx = 2.0f * tanhf(p0);
        const float my = 2.0f * tanhf(p1);
        float s = expf(tanhf(p2));
        s = fminf(fmaxf(s, 0.5f), 2.0f);
        const int ppy = blockIdx.y * 4 + (p >> 2);
        const int ppx = blockIdx.x * 4 + (p &  3);
        const int n = (b*HP + ppy)*HP + ppx;
        g_mx[n] = mx; g_my[n] = my; g_s[n] = s;
        out_scale[n] = s;
    }
}

// ============================================================================
// Kernel C: deformable sampling + mean + embed + LayerNorm.
// mean(bilerp(embed(x))) == embed(mean(bilerp(x))) by linearity/convexity.
// One warp per token; lanes 0..15 bilerp the 16 sample points on 3-ch input.
// ============================================================================
__global__ void __launch_bounds__(256) k_sample(const float* __restrict__ x,
                                                const float* __restrict__ ew,
                                                const float* __restrict__ eb,
                                                const float* __restrict__ lnw,
                                                const float* __restrict__ lnb,
                                                float* __restrict__ out_tokens)
{
    const int warp = (blockIdx.x * 256 + threadIdx.x) >> 5;
    const int lane = threadIdx.x & 31;
    if (warp >= Bc*NTOK) return;
    const int b  = warp / NTOK;
    const int n  = warp % NTOK;
    const int py = n / HP;
    const int px = n % HP;

    const float mx = g_mx[warp], my = g_my[warp], s = g_s[warp];
    const float cx = px*4 + 2.0f;
    const float cy = py*4 + 2.0f;
    const float half = s * 2.0f;

    const float x1 = fminf(fmaxf(cx + mx - half, 0.0f), 639.0f);
    const float x2 = fminf(fmaxf(cx + mx + half, 0.0f), 639.0f);
    const float y1 = fminf(fmaxf(cy + my - half, 0.0f), 639.0f);
    const float y2 = fminf(fmaxf(cy + my + half, 0.0f), 639.0f);

    float m0 = 0.f, m1 = 0.f, m2 = 0.f;
    if (lane < 16) {
        const int i = lane & 3;
        const int j = lane >> 2;
        const float xt = x1 + (x2 - x1) * (i * (1.0f/3.0f));
        const float yt = y1 + (y2 - y1) * (j * (1.0f/3.0f));
        const float xf = floorf(xt), yf = floorf(yt);
        const float wx = xt - xf,   wy = yt - yf;
        int X0i = min(max((int)xf, 0), IMG-1);
        int X1i = min(X0i + 1, IMG-1);
        int Y0i = min(max((int)yf, 0), IMG-1);
        int Y1i = min(Y0i + 1, IMG-1);
        const float w00 = (1.f-wx)*(1.f-wy), w01 = wx*(1.f-wy);
        const float w10 = (1.f-wx)*wy,       w11 = wx*wy;
        const float* xb = x + b*3*HW;
#pragma unroll
        for (int c = 0; c < 3; c++) {
            const float* f = xb + c*HW;
            float v = f[Y0i*IMG + X0i]*w00 + f[Y0i*IMG + X1i]*w01
                    + f[Y1i*IMG + X0i]*w10 + f[Y1i*IMG + X1i]*w11;
            if (c == 0) m0 = v; else if (c == 1) m1 = v; else m2 = v;
        }
    }
#pragma unroll
    for (int o = 16; o > 0; o >>= 1) {
        m0 += __shfl_xor_sync(0xFFFFFFFFu, m0, o);
        m1 += __shfl_xor_sync(0xFFFFFFFFu, m1, o);
        m2 += __shfl_xor_sync(0xFFFFFFFFu, m2, o);
    }
    m0 *= (1.0f/16.0f); m1 *= (1.0f/16.0f); m2 *= (1.0f/16.0f);

    float t[3];
#pragma unroll
    for (int r = 0; r < 3; r++) {
        int d = lane + 32*r;
        t[r] = ew[d*3+0]*m0 + ew[d*3+1]*m1 + ew[d*3+2]*m2 + eb[d];
    }
    float lsum = t[0] + t[1] + t[2];
#pragma unroll
    for (int o = 16; o > 0; o >>= 1) lsum += __shfl_xor_sync(0xFFFFFFFFu, lsum, o);
    const float mu = lsum * (1.0f/96.0f);
    float d0 = t[0]-mu, d1 = t[1]-mu, d2 = t[2]-mu;
    float lsq = d0*d0 + d1*d1 + d2*d2;
#pragma unroll
    for (int o = 16; o > 0; o >>= 1) lsq += __shfl_xor_sync(0xFFFFFFFFu, lsq, o);
    const float var = lsq * (1.0f/96.0f);
    const float inv = 1.0f / sqrtf(var + LN_EPS);

    float* outw = out_tokens + warp*Dc;
#pragma unroll
    for (int r = 0; r < 3; r++) {
        int d = lane + 32*r;
        outw[d] = (t[r] - mu) * inv * lnw[d] + lnb[d];
    }
}

// ============================================================================
extern "C" void kernel_launch(void* const* d_in, const int* in_sizes, int n_in,
                              void* d_out, int out_size) {
    const float* x   = (const float*)d_in[0];
    const float* ew  = (const float*)d_in[1];
    const float* eb  = (const float*)d_in[2];
    const float* w1  = (const float*)d_in[3];
    const float* b1  = (const float*)d_in[4];
    const float* w2  = (const float*)d_in[5];
    const float* b2  = (const float*)d_in[6];
    const float* lnw = (const float*)d_in[7];
    const float* lnb = (const float*)d_in[8];
    float* out = (float*)d_out;

    float* out_tokens = out;
    float* out_scale  = out + TOK_ELEMS;

    k_weff<<<30, 256>>>(ew, eb, w1, b1, w2);

    dim3 gfused(IMG/16, IMG/16, Bc);     // 40 x 40 x 2
    k_fused<<<gfused, 256>>>(x, b2, out_scale);

    k_sample<<<(Bc*NTOK*32 + 255)/256, 256>>>(x, ew, eb, lnw, lnb, out_tokens);
}

// round 4
// speedup vs baseline: 14.6507x; 1.1885x over previous
#include <cuda_runtime.h>

// ---------------- problem constants ----------------
#define IMG   640
#define HW    (IMG*IMG)
#define Bc    2
#define Dc    96
#define HP    160
#define NTOK  (HP*HP)            // 25600 tokens per batch
#define TOK_ELEMS (Bc*NTOK*Dc)   // 4,915,200
#define LN_EPS 1e-5f

typedef unsigned long long ull;

// ---------------- scratch (device globals; no allocs allowed) ----------------
__device__ ull   g_wp [48*37];       // folded conv weights, f32x2 do-pairs: [dp][tap] tap36=b1
__device__ ull   g_w2p[3*48*16];     // second-conv weights, f32x2 do-pairs: [o][dp][tap]
__device__ float g_mx[Bc*NTOK];
__device__ float g_my[Bc*NTOK];
__device__ float g_s [Bc*NTOK];

// ---------------- helpers ----------------
__device__ __forceinline__ ull pk2(float v) {
    ull r; asm("mov.b64 %0, {%1, %1};" : "=l"(r) : "f"(v)); return r;
}
__device__ __forceinline__ ull pack2(float a, float b) {
    ull r; asm("mov.b64 %0, {%1, %2};" : "=l"(r) : "f"(a), "f"(b)); return r;
}
__device__ __forceinline__ void fma2(ull& acc, ull a, ull b) {
    asm("fma.rn.f32x2 %0, %1, %2, %0;" : "+l"(acc) : "l"(a), "l"(b));
}
__device__ __forceinline__ ull add2(ull a, ull b) {
    ull r; asm("add.rn.f32x2 %0, %1, %2;" : "=l"(r) : "l"(a), "l"(b)); return r;
}
__device__ __forceinline__ float2 upk2(ull v) {
    float2 r; asm("mov.b64 {%0, %1}, %2;" : "=f"(r.x), "=f"(r.y) : "l"(v)); return r;
}

// Exact-GELU with fast path: pre-GELU h values here have std ~0.023 (weights
// ~0.02), so |v| < 0.7 essentially always. 5-term odd Taylor of erf(v/sqrt(2))
// has abs error < 1e-6 on |v|<=0.7; rare tails fall back to erff (branch,
// near-zero divergence probability).
__device__ __forceinline__ float gelu_fast(float v) {
    const float t = v * 0.7071067811865476f;
    const float u = t * t;
    // erf(t) = (2/sqrt(pi)) * t * (1 - u/3 + u^2/10 - u^3/42 + u^4/216)
    float p = 1.1283791670955126f * t *
              (1.0f + u * (-0.33333333333f + u * (0.1f + u * (-0.023809523810f + u * 0.0046296296296f))));
    if (u > 0.25f) p = erff(t);   // |v| > ~0.707: exact fallback
    return 0.5f * v * (1.0f + p);
}

// ============================================================================
// Kernel A: fold embed (1x1) into the 3x3 conv -> w_eff over 4 channels.
// Warp-per-output over the 48x37 folded table (lane-parallel di reduction,
// MLP~32); tail blocks repack w2 thread-per-element.
// ============================================================================
#define WEFF_WARP_BLOCKS 222   // 222*8 warps = 1776 = 48*37
__global__ void __launch_bounds__(256) k_weff(const float* __restrict__ ew,  // [96][3]
                                              const float* __restrict__ eb,  // [96]
                                              const float* __restrict__ w1,  // [96][96][3][3]
                                              const float* __restrict__ b1,  // [96]
                                              const float* __restrict__ w2)  // [3][96][4][4]
{
    const int bid = blockIdx.x;
    if (bid < WEFF_WARP_BLOCKS) {
        const int wid  = bid * 8 + (threadIdx.x >> 5);
        const int lane = threadIdx.x & 31;
        const int dp = wid / 37, t = wid % 37;
        if (t == 36) {
            if (lane == 0) g_wp[wid] = pack2(b1[2*dp], b1[2*dp+1]);
            return;
        }
        const int c = t / 9, kk = t % 9;
        float v0 = 0.f, v1 = 0.f;
#pragma unroll
        for (int r = 0; r < 3; r++) {
            const int di = lane + 32*r;
            const float e = (c < 3) ? ew[di*3 + c] : eb[di];
            v0 = fmaf(w1[((2*dp    )*Dc + di)*9 + kk], e, v0);
            v1 = fmaf(w1[((2*dp + 1)*Dc + di)*9 + kk], e, v1);
        }
#pragma unroll
        for (int o = 16; o > 0; o >>= 1) {
            v0 += __shfl_xor_sync(0xFFFFFFFFu, v0, o);
            v1 += __shfl_xor_sync(0xFFFFFFFFu, v1, o);
        }
        if (lane == 0) g_wp[wid] = pack2(v0, v1);
    } else {
        const int i = (bid - WEFF_WARP_BLOCKS) * 256 + threadIdx.x;
        if (i < 3*48*16) {
            const int tap = i & 15;
            const int dp  = (i >> 4) % 48;
            const int o   = i / (48*16);
            g_w2p[i] = pack2(w2[(o*Dc + 2*dp    )*16 + tap],
                             w2[(o*Dc + 2*dp + 1)*16 + tap]);
        }
    }
}

// ============================================================================
// Kernel B: fully fused  conv3x3(4ch) + GELU + conv4x4-stride4 + transforms.
// CTA = 16x16 h-pixels = 4x4 params. Thread = one h pixel (36-reg x patch),
// loops 48 do-pairs with f32x2; contracts GELU'd h directly into 3 params.
// ============================================================================
__global__ void __launch_bounds__(256) k_fused(const float* __restrict__ x,
                                               const float* __restrict__ b2,
                                               float* __restrict__ out_scale)
{
    __shared__ float sx[4][18][20];     // [c][row][col] halo tile (+pad)
    __shared__ ull   swp[48][37];       // folded conv weight pairs (+bias)
    __shared__ ull   sw2p[3][48][16];   // second conv weight pairs

    const int tid = threadIdx.x;
    const int b   = blockIdx.z;
    const int X0  = blockIdx.x * 16;
    const int Y0  = blockIdx.y * 16;

    for (int i = tid; i < 4*18*18; i += 256) {
        const int c   = i / (18*18);
        const int r   = (i / 18) % 18;
        const int col = i % 18;
        const int gy = Y0 - 1 + r;
        const int gx = X0 - 1 + col;
        const bool in = ((unsigned)gy < (unsigned)IMG) && ((unsigned)gx < (unsigned)IMG);
        float v;
        if (c < 3) v = in ? x[((b*3 + c)*IMG + gy)*IMG + gx] : 0.f;
        else       v = in ? 1.f : 0.f;
        sx[c][r][col] = v;
    }
    for (int i = tid; i < 48*37;   i += 256) ((ull*)swp )[i] = g_wp[i];
    for (int i = tid; i < 3*48*16; i += 256) ((ull*)sw2p)[i] = g_w2p[i];
    __syncthreads();

    const int p   = tid >> 4;          // param within CTA (0..15)
    const int tap = tid & 15;          // position within 4x4 patch
    const int hy  = (p >> 2) * 4 + (tap >> 2);
    const int hx  = (p &  3) * 4 + (tap &  3);

    // register-cache the 4x3x3 input patch, pre-broadcast to f32x2
    ull xp2[36];
#pragma unroll
    for (int c = 0; c < 4; c++)
#pragma unroll
        for (int ky = 0; ky < 3; ky++)
#pragma unroll
            for (int kx = 0; kx < 3; kx++)
                xp2[c*9 + ky*3 + kx] = pk2(sx[c][hy + ky][hx + kx]);

    ull pa0 = 0ULL, pa1 = 0ULL, pa2 = 0ULL;
#pragma unroll 2
    for (int dp = 0; dp < 48; dp++) {
        ull a0 = swp[dp][36];          // (b1[2dp], b1[2dp+1]) pre-gelu bias
        ull a1 = 0ULL;
#pragma unroll
        for (int t = 0; t < 36; t += 2) {
            fma2(a0, xp2[t],     swp[dp][t]);
            fma2(a1, xp2[t + 1], swp[dp][t + 1]);
        }
        const float2 hv = upk2(add2(a0, a1));
        const ull hp = pack2(gelu_fast(hv.x), gelu_fast(hv.y));
        fma2(pa0, hp, sw2p[0][dp][tap]);
        fma2(pa1, hp, sw2p[1][dp][tap]);
        fma2(pa2, hp, sw2p[2][dp][tap]);
    }

    const float2 q0 = upk2(pa0), q1 = upk2(pa1), q2 = upk2(pa2);
    float p0 = q0.x + q0.y;
    float p1 = q1.x + q1.y;
    float p2 = q2.x + q2.y;
#pragma unroll
    for (int off = 8; off > 0; off >>= 1) {
        p0 += __shfl_down_sync(0xFFFFFFFFu, p0, off, 16);
        p1 += __shfl_down_sync(0xFFFFFFFFu, p1, off, 16);
        p2 += __shfl_down_sync(0xFFFFFFFFu, p2, off, 16);
    }
    if (tap == 0) {
        p0 += b2[0]; p1 += b2[1]; p2 += b2[2];
        const float mx = 2.0f * tanhf(p0);
        const float my = 2.0f * tanhf(p1);
        float s = expf(tanhf(p2));
        s = fminf(fmaxf(s, 0.5f), 2.0f);
        const int ppy = blockIdx.y * 4 + (p >> 2);
        const int ppx = blockIdx.x * 4 + (p &  3);
        const int n = (b*HP + ppy)*HP + ppx;
        g_mx[n] = mx; g_my[n] = my; g_s[n] = s;
        out_scale[n] = s;
    }
}

// ============================================================================
// Kernel C: deformable sampling + mean + embed + LayerNorm.
// mean(bilerp(embed(x))) == embed(mean(bilerp(x))) by linearity/convexity.
// TWO tokens per warp (half-warp each): all 32 lanes gather (16 sample points
// per token), width-16 reduces, then 6 embed channels per lane + LN.
// ============================================================================
__global__ void __launch_bounds__(256) k_sample(const float* __restrict__ x,
                                                const float* __restrict__ ew,
                                                const float* __restrict__ eb,
                                                const float* __restrict__ lnw,
                                                const float* __restrict__ lnb,
                                                float* __restrict__ out_tokens)
{
    const int warp = (blockIdx.x * 256 + threadIdx.x) >> 5;
    const int lane = threadIdx.x & 31;
    const int half = lane >> 4;            // which token within warp
    const int hl   = lane & 15;            // lane within half-warp
    const int n_g  = warp * 2 + half;      // global token id (b*NTOK + n)
    if (n_g >= Bc*NTOK) return;
    const int b  = n_g / NTOK;
    const int n  = n_g % NTOK;
    const int py = n / HP;
    const int px = n % HP;

    const float mx = g_mx[n_g], my = g_my[n_g], s = g_s[n_g];
    const float cx = px*4 + 2.0f;
    const float cy = py*4 + 2.0f;
    const float halfw = s * 2.0f;

    const float x1 = fminf(fmaxf(cx + mx - halfw, 0.0f), 639.0f);
    const float x2 = fminf(fmaxf(cx + mx + halfw, 0.0f), 639.0f);
    const float y1 = fminf(fmaxf(cy + my - halfw, 0.0f), 639.0f);
    const float y2 = fminf(fmaxf(cy + my + halfw, 0.0f), 639.0f);

    const int i = hl & 3;                  // x index within 4x4 samples
    const int j = hl >> 2;                 // y index
    const float xt = x1 + (x2 - x1) * (i * (1.0f/3.0f));
    const float yt = y1 + (y2 - y1) * (j * (1.0f/3.0f));
    const float xf = floorf(xt), yf = floorf(yt);
    const float wx = xt - xf,   wy = yt - yf;
    int X0i = min(max((int)xf, 0), IMG-1);
    int X1i = min(X0i + 1, IMG-1);
    int Y0i = min(max((int)yf, 0), IMG-1);
    int Y1i = min(Y0i + 1, IMG-1);
    const float w00 = (1.f-wx)*(1.f-wy), w01 = wx*(1.f-wy);
    const float w10 = (1.f-wx)*wy,       w11 = wx*wy;
    const float* xb = x + b*3*HW;

    float m0, m1, m2;
#pragma unroll
    for (int c = 0; c < 3; c++) {
        const float* f = xb + c*HW;
        float v = f[Y0i*IMG + X0i]*w00 + f[Y0i*IMG + X1i]*w01
                + f[Y1i*IMG + X0i]*w10 + f[Y1i*IMG + X1i]*w11;
        if (c == 0) m0 = v; else if (c == 1) m1 = v; else m2 = v;
    }
#pragma unroll
    for (int o = 8; o > 0; o >>= 1) {
        m0 += __shfl_xor_sync(0xFFFFFFFFu, m0, o);
        m1 += __shfl_xor_sync(0xFFFFFFFFu, m1, o);
        m2 += __shfl_xor_sync(0xFFFFFFFFu, m2, o);
    }
    m0 *= (1.0f/16.0f); m1 *= (1.0f/16.0f); m2 *= (1.0f/16.0f);

    // embed: 6 output channels per lane (d = hl + 16*r), within half-warp
    float t[6];
    float lsum = 0.f;
#pragma unroll
    for (int r = 0; r < 6; r++) {
        int d = hl + 16*r;
        t[r] = ew[d*3+0]*m0 + ew[d*3+1]*m1 + ew[d*3+2]*m2 + eb[d];
        lsum += t[r];
    }
#pragma unroll
    for (int o = 8; o > 0; o >>= 1) lsum += __shfl_xor_sync(0xFFFFFFFFu, lsum, o);
    const float mu = lsum * (1.0f/96.0f);
    float lsq = 0.f;
#pragma unroll
    for (int r = 0; r < 6; r++) { float d = t[r]-mu; lsq += d*d; }
#pragma unroll
    for (int o = 8; o > 0; o >>= 1) lsq += __shfl_xor_sync(0xFFFFFFFFu, lsq, o);
    const float var = lsq * (1.0f/96.0f);
    const float inv = 1.0f / sqrtf(var + LN_EPS);

    float* outw = out_tokens + (size_t)n_g*Dc;
#pragma unroll
    for (int r = 0; r < 6; r++) {
        int d = hl + 16*r;
        outw[d] = (t[r] - mu) * inv * lnw[d] + lnb[d];
    }
}

// ============================================================================
extern "C" void kernel_launch(void* const* d_in, const int* in_sizes, int n_in,
                              void* d_out, int out_size) {
    const float* x   = (const float*)d_in[0];
    const float* ew  = (const float*)d_in[1];
    const float* eb  = (const float*)d_in[2];
    const float* w1  = (const float*)d_in[3];
    const float* b1  = (const float*)d_in[4];
    const float* w2  = (const float*)d_in[5];
    const float* b2  = (const float*)d_in[6];
    const float* lnw = (const float*)d_in[7];
    const float* lnb = (const float*)d_in[8];
    float* out = (float*)d_out;

    float* out_tokens = out;
    float* out_scale  = out + TOK_ELEMS;

    k_weff<<<WEFF_WARP_BLOCKS + 9, 256>>>(ew, eb, w1, b1, w2);

    dim3 gfused(IMG/16, IMG/16, Bc);     // 40 x 40 x 2
    k_fused<<<gfused, 256>>>(x, b2, out_scale);

    // 2 tokens per warp -> Bc*NTOK/2 warps
    k_sample<<<(Bc*NTOK/2*32 + 255)/256, 256>>>(x, ew, eb, lnw, lnb, out_tokens);
}